// round 11
// baseline (speedup 1.0000x reference)
#include <cuda_runtime.h>
#include <cuda_bf16.h>
#include <cstdint>

// ---------------- problem constants ----------------
#define B_SZ   4
#define SEQ    2048
#define DM     1024      // d_model
#define NS     16        // state
#define MROWS  (B_SZ*SEQ)      // 8192
#define CHUNK  32
#define NCH    (SEQ/CHUNK)     // 64

// ---------------- device scratch (static: no allocs allowed) ----------------
__device__ float g_delta[(size_t)MROWS * DM];          // softplus(x@Wd+bd)
__device__ float g_Bm[(size_t)MROWS * NS];
__device__ float g_Cm[(size_t)MROWS * NS];
__device__ float g_hloc[(size_t)B_SZ * DM * NCH * NS]; // chunk-local end states (h_in=0)
__device__ float g_hin [(size_t)B_SZ * DM * NCH * NS]; // propagated chunk-start states
__device__ float g_S   [(size_t)B_SZ * DM * NCH];      // per-chunk sum of delta

__device__ __forceinline__ float ex2f(float x) {
    float y;
    asm("ex2.approx.f32 %0, %1;" : "=f"(y) : "f"(x));
    return y;
}
__device__ __forceinline__ float lg2f(float x) {
    float y;
    asm("lg2.approx.f32 %0, %1;" : "=f"(y) : "f"(x));
    return y;
}

#define LOG2E 1.4426950408889634f
#define LN2   0.6931471805599453f

// fast stable softplus: max(z,0) + log2(1 + 2^(-|z|*log2e)) * ln2
// abs error <= ~1e-7 vs exact; matches jax.nn.softplus within fp32 noise.
__device__ __forceinline__ float softplusf(float z) {
    float e = ex2f(-fabsf(z) * LOG2E);       // exp(-|z|)
    return fmaxf(z, 0.0f) + lg2f(1.0f + e) * LN2;
}

__device__ __forceinline__ void cp_async16(void* smem_dst, const void* gmem_src) {
    uint32_t s = (uint32_t)__cvta_generic_to_shared(smem_dst);
    asm volatile("cp.async.cg.shared.global [%0], [%1], 16;\n" :: "r"(s), "l"(gmem_src));
}
__device__ __forceinline__ void cp_async_commit() {
    asm volatile("cp.async.commit_group;\n");
}
__device__ __forceinline__ void cp_async_wait0() {
    asm volatile("cp.async.wait_group 0;\n");
}

// round fp32 -> tf32 (RNA); result readable as fp32 with low mantissa zeroed
__device__ __forceinline__ uint32_t f2tf32(float v) {
    uint32_t r;
    asm("cvt.rna.tf32.f32 %0, %1;" : "=r"(r) : "f"(v));
    return r;
}

// D += A(16x8,row) * B(8x8,col), tf32 inputs, fp32 accum
__device__ __forceinline__ void mma_tf32(float c[4], const uint32_t a[4], const uint32_t b[2]) {
    asm volatile(
        "mma.sync.aligned.m16n8k8.row.col.f32.tf32.tf32.f32 "
        "{%0,%1,%2,%3}, {%4,%5,%6,%7}, {%8,%9}, {%0,%1,%2,%3};"
        : "+f"(c[0]), "+f"(c[1]), "+f"(c[2]), "+f"(c[3])
        : "r"(a[0]), "r"(a[1]), "r"(a[2]), "r"(a[3]), "r"(b[0]), "r"(b[1]));
}

// ---------------- kernel 1: delta = softplus(x @ Wd + bd) ----------------
// tensor-core GEMM (3xTF32 split), BM=BN=128, BK=16, 256 threads (8 warps),
// warp tile 64x32 (4 m-tiles x 4 n-tiles of m16n8k8), cp.async double buffer.
#define A_LDS 20    // padded row stride (floats) for As
#define B_LDS 132   // padded row stride (floats) for Bs
__global__ __launch_bounds__(256)
void gemm_delta_kernel(const float* __restrict__ X,   // (MROWS, DM)
                       const float* __restrict__ Wd,  // (DM, DM) row-major [k][n]
                       const float* __restrict__ bd)  // (DM,)
{
    __shared__ float As[2][128][A_LDS];   // [m][k], padded
    __shared__ float Bs[2][16][B_LDS];    // [k][n], padded

    const int tid = threadIdx.x;
    const int m0 = blockIdx.y * 128;
    const int n0 = blockIdx.x * 128;

    const int warp = tid >> 5;
    const int lane = tid & 31;
    const int g  = lane >> 2;      // group 0..7
    const int t4 = lane & 3;       // 0..3
    const int m0w = (warp & 1) * 64;   // warp m offset in block tile
    const int n0w = (warp >> 1) * 32;  // warp n offset in block tile

    // per-thread copy indices (2 float4s per tile per operand)
    const int idx0 = tid, idx1 = tid + 256;
    const int a_row0 = idx0 >> 2, a_k0 = (idx0 & 3) * 4;
    const int a_row1 = idx1 >> 2, a_k1 = (idx1 & 3) * 4;
    const int b_kr0 = idx0 >> 5, b_n0 = (idx0 & 31) * 4;
    const int b_kr1 = idx1 >> 5, b_n1 = (idx1 & 31) * 4;

    float acc[4][4][4];   // [m-tile][n-tile][frag]
    #pragma unroll
    for (int i = 0; i < 4; i++)
        #pragma unroll
        for (int j = 0; j < 4; j++)
            #pragma unroll
            for (int r = 0; r < 4; r++) acc[i][j][r] = 0.0f;

    // prologue: tile 0 -> buffer 0
    {
        cp_async16(&As[0][a_row0][a_k0], &X[(size_t)(m0 + a_row0) * DM + a_k0]);
        cp_async16(&As[0][a_row1][a_k1], &X[(size_t)(m0 + a_row1) * DM + a_k1]);
        cp_async16(&Bs[0][b_kr0][b_n0], &Wd[(size_t)b_kr0 * DM + n0 + b_n0]);
        cp_async16(&Bs[0][b_kr1][b_n1], &Wd[(size_t)b_kr1 * DM + n0 + b_n1]);
        cp_async_commit();
        cp_async_wait0();
    }
    __syncthreads();

    const int NT = DM / 16;   // 64 k-tiles
    #pragma unroll 1
    for (int t = 0; t < NT; t++) {
        const int cur = t & 1;
        if (t + 1 < NT) {
            const int nxt = cur ^ 1;
            const int k0 = (t + 1) * 16;
            cp_async16(&As[nxt][a_row0][a_k0], &X[(size_t)(m0 + a_row0) * DM + k0 + a_k0]);
            cp_async16(&As[nxt][a_row1][a_k1], &X[(size_t)(m0 + a_row1) * DM + k0 + a_k1]);
            cp_async16(&Bs[nxt][b_kr0][b_n0], &Wd[(size_t)(k0 + b_kr0) * DM + n0 + b_n0]);
            cp_async16(&Bs[nxt][b_kr1][b_n1], &Wd[(size_t)(k0 + b_kr1) * DM + n0 + b_n1]);
            cp_async_commit();
        }

        #pragma unroll
        for (int k8 = 0; k8 < 16; k8 += 8) {
            // ---- load + split A fragments (4 m-tiles) ----
            uint32_t ah[4][4], al[4][4];
            #pragma unroll
            for (int mt = 0; mt < 4; mt++) {
                const float* r0 = &As[cur][m0w + mt * 16 + g][k8];
                const float* r1 = r0 + 8 * A_LDS;   // row + 8
                float v0 = r0[t4], v1 = r1[t4], v2 = r0[t4 + 4], v3 = r1[t4 + 4];
                ah[mt][0] = f2tf32(v0); al[mt][0] = f2tf32(__fsub_rn(v0, __uint_as_float(ah[mt][0])));
                ah[mt][1] = f2tf32(v1); al[mt][1] = f2tf32(__fsub_rn(v1, __uint_as_float(ah[mt][1])));
                ah[mt][2] = f2tf32(v2); al[mt][2] = f2tf32(__fsub_rn(v2, __uint_as_float(ah[mt][2])));
                ah[mt][3] = f2tf32(v3); al[mt][3] = f2tf32(__fsub_rn(v3, __uint_as_float(ah[mt][3])));
            }
            // ---- load + split B fragments (4 n-tiles) ----
            uint32_t bh[4][2], bl[4][2];
            #pragma unroll
            for (int nt = 0; nt < 4; nt++) {
                const int col = n0w + nt * 8 + g;
                float v0 = Bs[cur][k8 + t4][col];
                float v1 = Bs[cur][k8 + t4 + 4][col];
                bh[nt][0] = f2tf32(v0); bl[nt][0] = f2tf32(__fsub_rn(v0, __uint_as_float(bh[nt][0])));
                bh[nt][1] = f2tf32(v1); bl[nt][1] = f2tf32(__fsub_rn(v1, __uint_as_float(bh[nt][1])));
            }
            // ---- 3-pass mma: hi*hi, hi*lo, lo*hi ----
            #pragma unroll
            for (int mt = 0; mt < 4; mt++)
                #pragma unroll
                for (int nt = 0; nt < 4; nt++) {
                    mma_tf32(acc[mt][nt], ah[mt], bh[nt]);
                    mma_tf32(acc[mt][nt], ah[mt], bl[nt]);
                    mma_tf32(acc[mt][nt], al[mt], bh[nt]);
                }
        }

        if (t + 1 < NT) cp_async_wait0();
        __syncthreads();
    }

    // epilogue: bias + softplus
    #pragma unroll
    for (int mt = 0; mt < 4; mt++) {
        const int r0 = m0 + m0w + mt * 16 + g;
        const int r1 = r0 + 8;
        #pragma unroll
        for (int nt = 0; nt < 4; nt++) {
            const int cbase = n0 + n0w + nt * 8 + 2 * t4;
            const float b0 = __ldg(&bd[cbase]), b1 = __ldg(&bd[cbase + 1]);
            float2 v0, v1;
            v0.x = softplusf(acc[mt][nt][0] + b0);
            v0.y = softplusf(acc[mt][nt][1] + b1);
            v1.x = softplusf(acc[mt][nt][2] + b0);
            v1.y = softplusf(acc[mt][nt][3] + b1);
            *(float2*)&g_delta[(size_t)r0 * DM + cbase] = v0;
            *(float2*)&g_delta[(size_t)r1 * DM + cbase] = v1;
        }
    }
}

// ---------------- kernel 2: Bm = x@Wb+bb, Cm = x@Wc+bc (N=16 each) ----------------
#define BC_BK 128
__global__ __launch_bounds__(256)
void proj_bc_kernel(const float* __restrict__ X,
                    const float* __restrict__ Wb, const float* __restrict__ bb,
                    const float* __restrict__ Wc, const float* __restrict__ bc)
{
    __shared__ float xs[16][BC_BK];    // 8KB
    __shared__ float ws[BC_BK][32];    // 16KB
    const int row0 = blockIdx.x * 16;
    const int c  = threadIdx.x & 31;   // 0..31 (0..15 -> B, 16..31 -> C)
    const int rq = threadIdx.x >> 5;   // 0..7

    float acc0 = 0.0f, acc1 = 0.0f;
    for (int k0 = 0; k0 < DM; k0 += BC_BK) {
        #pragma unroll
        for (int it = 0; it < 2; it++) {
            int i = threadIdx.x + it * 256;     // 0..511 float4s of xs
            int r  = i / (BC_BK / 4);
            int kk = i % (BC_BK / 4);
            *(float4*)&xs[r][kk * 4] =
                *(const float4*)&X[(size_t)(row0 + r) * DM + k0 + kk * 4];
        }
        for (int i = threadIdx.x; i < BC_BK * 32; i += 256) {
            int kk = i >> 5, cc = i & 31;
            ws[kk][cc] = (cc < 16) ? Wb[(size_t)(k0 + kk) * NS + cc]
                                   : Wc[(size_t)(k0 + kk) * NS + (cc - 16)];
        }
        __syncthreads();
        #pragma unroll 8
        for (int k = 0; k < BC_BK; k++) {
            float w = ws[k][c];
            acc0 += xs[rq][k] * w;
            acc1 += xs[rq + 8][k] * w;
        }
        __syncthreads();
    }
    const int r0 = row0 + rq, r1 = row0 + rq + 8;
    if (c < 16) {
        g_Bm[(size_t)r0 * NS + c] = acc0 + bb[c];
        g_Bm[(size_t)r1 * NS + c] = acc1 + bb[c];
    } else {
        g_Cm[(size_t)r0 * NS + (c - 16)] = acc0 + bc[c - 16];
        g_Cm[(size_t)r1 * NS + (c - 16)] = acc1 + bc[c - 16];
    }
}

// ---------------- kernel 3: chunked scan pass 1 (local states, h_in = 0) ----------------
__global__ __launch_bounds__(128)
void scan_pass1_kernel(const float* __restrict__ X, const float* __restrict__ A_log)
{
    const int d = blockIdx.x * 128 + threadIdx.x;
    const int c = blockIdx.y;
    const int b = blockIdx.z;

    __shared__ float Bs[CHUNK][NS];    // 2KB
    {
        const float* src = &g_Bm[((size_t)b * SEQ + c * CHUNK) * NS];
        for (int i = threadIdx.x; i < CHUNK * NS; i += 128)
            Bs[i / NS][i % NS] = src[i];
    }
    __syncthreads();

    float A2[NS];
    #pragma unroll
    for (int n = 0; n < NS; n++)
        A2[n] = -__expf(A_log[d * NS + n]) * LOG2E;

    float h[NS];
    #pragma unroll
    for (int n = 0; n < NS; n++) h[n] = 0.0f;
    float S = 0.0f;

    const size_t rowbase = ((size_t)b * SEQ + c * CHUNK) * DM + d;
    const float* dp = g_delta + rowbase;
    const float* xp = X + rowbase;

    #pragma unroll 4
    for (int t = 0; t < CHUNK; t++) {
        float dt  = dp[(size_t)t * DM];
        float xt  = xp[(size_t)t * DM];
        float dtx = dt * xt;
        S += dt;
        #pragma unroll
        for (int n = 0; n < NS; n++) {
            float barA = ex2f(dt * A2[n]);
            h[n] = barA * h[n] + dtx * Bs[t][n];
        }
    }

    const size_t base = (((size_t)b * DM + d) * NCH + c) * NS;
    #pragma unroll
    for (int n = 0; n < NS; n += 4)
        *(float4*)&g_hloc[base + n] = make_float4(h[n], h[n+1], h[n+2], h[n+3]);
    g_S[((size_t)b * DM + d) * NCH + c] = S;
}

// ---------------- kernel 4: sequential chunk combine (n-parallel) ----------------
__global__ __launch_bounds__(256)
void combine_kernel(const float* __restrict__ A_log)
{
    const int idx = blockIdx.x * 256 + threadIdx.x;   // 0..65535
    const int n  = idx & (NS - 1);
    const int bd = idx >> 4;                          // b*DM + d
    const int d  = bd & (DM - 1);

    const float A2 = -__expf(A_log[d * NS + n]) * LOG2E;
    float h = 0.0f;
    const size_t sbase = (size_t)bd * NCH;
    for (int c = 0; c < NCH; c++) {
        g_hin[(sbase + c) * NS + n] = h;
        h = ex2f(A2 * g_S[sbase + c]) * h + g_hloc[(sbase + c) * NS + n];
    }
}

// ---------------- kernel 5: chunked scan pass 2 (real h_in, emit y) ----------------
__global__ __launch_bounds__(128)
void scan_pass2_kernel(const float* __restrict__ X, const float* __restrict__ A_log,
                       const float* __restrict__ D_skip, float* __restrict__ out)
{
    const int d = blockIdx.x * 128 + threadIdx.x;
    const int c = blockIdx.y;
    const int b = blockIdx.z;

    __shared__ float Bs[CHUNK][NS];
    __shared__ float Cs[CHUNK][NS];
    {
        const float* srcB = &g_Bm[((size_t)b * SEQ + c * CHUNK) * NS];
        const float* srcC = &g_Cm[((size_t)b * SEQ + c * CHUNK) * NS];
        for (int i = threadIdx.x; i < CHUNK * NS; i += 128) {
            Bs[i / NS][i % NS] = srcB[i];
            Cs[i / NS][i % NS] = srcC[i];
        }
    }
    __syncthreads();

    float A2[NS];
    #pragma unroll
    for (int n = 0; n < NS; n++)
        A2[n] = -__expf(A_log[d * NS + n]) * LOG2E;

    float h[NS];
    {
        const size_t base = (((size_t)b * DM + d) * NCH + c) * NS;
        #pragma unroll
        for (int n = 0; n < NS; n += 4) {
            float4 v = *(const float4*)&g_hin[base + n];
            h[n] = v.x; h[n+1] = v.y; h[n+2] = v.z; h[n+3] = v.w;
        }
    }
    const float dsk = D_skip[d];

    const size_t rowbase = ((size_t)b * SEQ + c * CHUNK) * DM + d;
    const float* dp = g_delta + rowbase;
    const float* xp = X + rowbase;
    float* op = out + rowbase;

    #pragma unroll 4
    for (int t = 0; t < CHUNK; t++) {
        float dt  = dp[(size_t)t * DM];
        float xt  = xp[(size_t)t * DM];
        float dtx = dt * xt;
        float y = xt * dsk;
        #pragma unroll
        for (int n = 0; n < NS; n++) {
            float barA = ex2f(dt * A2[n]);
            h[n] = barA * h[n] + dtx * Bs[t][n];
            y += h[n] * Cs[t][n];
        }
        op[(size_t)t * DM] = y;
    }
}

// ---------------- launch ----------------
extern "C" void kernel_launch(void* const* d_in, const int* in_sizes, int n_in,
                              void* d_out, int out_size)
{
    const float* x      = (const float*)d_in[0];
    const float* A_log  = (const float*)d_in[1];
    const float* D_skip = (const float*)d_in[2];
    const float* Wd     = (const float*)d_in[3];
    const float* bd     = (const float*)d_in[4];
    const float* Wb     = (const float*)d_in[5];
    const float* bb     = (const float*)d_in[6];
    const float* Wc     = (const float*)d_in[7];
    const float* bc     = (const float*)d_in[8];
    float* out = (float*)d_out;

    gemm_delta_kernel<<<dim3(DM / 128, MROWS / 128), 256>>>(x, Wd, bd);
    proj_bc_kernel<<<MROWS / 16, 256>>>(x, Wb, bb, Wc, bc);
    scan_pass1_kernel<<<dim3(DM / 128, NCH, B_SZ), 128>>>(x, A_log);
    combine_kernel<<<(B_SZ * DM * NS) / 256, 256>>>(A_log);
    scan_pass2_kernel<<<dim3(DM / 128, NCH, B_SZ), 128>>>(x, A_log, D_skip, out);
}

// round 13
// speedup vs baseline: 1.5661x; 1.5661x over previous
#include <cuda_runtime.h>
#include <cuda_bf16.h>
#include <cstdint>

// ---------------- problem constants ----------------
#define B_SZ   4
#define SEQ    2048
#define DM     1024      // d_model
#define NS     16        // state
#define MROWS  (B_SZ*SEQ)      // 8192
#define CHUNK  32
#define NCH    (SEQ/CHUNK)     // 64

// ---------------- device scratch (static: no allocs allowed) ----------------
__device__ float g_delta[(size_t)MROWS * DM];          // softplus(x@Wd+bd)
__device__ float g_Bm[(size_t)MROWS * NS];
__device__ float g_Cm[(size_t)MROWS * NS];
__device__ float g_hloc[(size_t)B_SZ * DM * NCH * NS]; // chunk-local end states (h_in=0)
__device__ float g_hin [(size_t)B_SZ * DM * NCH * NS]; // propagated chunk-start states
__device__ float g_S   [(size_t)B_SZ * DM * NCH];      // per-chunk sum of delta

__device__ __forceinline__ float ex2f(float x) {
    float y;
    asm("ex2.approx.f32 %0, %1;" : "=f"(y) : "f"(x));
    return y;
}
__device__ __forceinline__ float lg2f(float x) {
    float y;
    asm("lg2.approx.f32 %0, %1;" : "=f"(y) : "f"(x));
    return y;
}

#define LOG2E 1.4426950408889634f
#define LN2   0.6931471805599453f

// fast stable softplus: max(z,0) + log2(1 + 2^(-|z|*log2e)) * ln2
__device__ __forceinline__ float softplusf(float z) {
    float e = ex2f(-fabsf(z) * LOG2E);       // exp(-|z|)
    return fmaxf(z, 0.0f) + lg2f(1.0f + e) * LN2;
}

__device__ __forceinline__ uint32_t packbf2(float x, float y) {
    __nv_bfloat162 p = __floats2bfloat162_rn(x, y);   // x -> low half (element 0)
    return *reinterpret_cast<uint32_t*>(&p);
}
// split (v0,v1) into hi bf16x2 and lo bf16x2 (lo = residual, bf16-rounded)
__device__ __forceinline__ void split2(float v0, float v1, uint32_t& hi, uint32_t& lo) {
    float h0 = __bfloat162float(__float2bfloat16_rn(v0));
    float h1 = __bfloat162float(__float2bfloat16_rn(v1));
    hi = packbf2(h0, h1);
    lo = packbf2(v0 - h0, v1 - h1);
}

// D += A(16x16,row) * B(16x8,col), bf16 inputs, fp32 accum
__device__ __forceinline__ void mma_bf16(float c[4], const uint32_t a[4], const uint32_t b[2]) {
    asm volatile(
        "mma.sync.aligned.m16n8k16.row.col.f32.bf16.bf16.f32 "
        "{%0,%1,%2,%3}, {%4,%5,%6,%7}, {%8,%9}, {%0,%1,%2,%3};"
        : "+f"(c[0]), "+f"(c[1]), "+f"(c[2]), "+f"(c[3])
        : "r"(a[0]), "r"(a[1]), "r"(a[2]), "r"(a[3]), "r"(b[0]), "r"(b[1]));
}

// ---------------- kernel 1: delta = softplus(x @ Wd + bd) ----------------
// bf16 2-term-split tensor-core GEMM (3 passes: hh + hl + lh), BM=BN=128,
// BK=16 (one m16n8k16 step per tile), 256 threads (8 warps), warp tile 64x32.
// fp32->bf16 hi/lo conversion happens ONCE at smem landing.
// Smem layout: [kpair][row] with row-stride 136 words (136 mod 32 == 8) ->
// fragment loads are bank-conflict-free: bank = (t4*8 + g + const) mod 32.
#define KPS 136   // padded row length (uint32) per kpair
__global__ __launch_bounds__(256)
void gemm_delta_kernel(const float* __restrict__ X,   // (MROWS, DM)
                       const float* __restrict__ Wd,  // (DM, DM) row-major [k][n]
                       const float* __restrict__ bd)  // (DM,)
{
    // [buf][kpair][m-row or n-col] packed bf16x2. 4*2*8*136*4B = 34.8KB.
    __shared__ uint32_t Ah[2][8][KPS], Al[2][8][KPS];
    __shared__ uint32_t Bh[2][8][KPS], Bl[2][8][KPS];

    const int tid = threadIdx.x;
    const int m0 = blockIdx.y * 128;
    const int n0 = blockIdx.x * 128;

    const int warp = tid >> 5;
    const int lane = tid & 31;
    const int g  = lane >> 2;          // 0..7
    const int t4 = lane & 3;           // 0..3
    const int m0w = (warp & 1) * 64;
    const int n0w = (warp >> 1) * 32;

    // A fill: rows ar0 / ar0+64, fp32 cols [akp*2 .. akp*2+3] (one float4 each)
    const int ar0 = tid >> 2;               // 0..63
    const int ar1 = ar0 + 64;
    const int akp = (tid & 3) * 2;          // kpair base: 0,2,4,6
    const int ak  = akp * 2;                // fp32 col base
    // B fill: thread -> one n column, 4 k-pairs
    const int bn  = tid & 127;
    const int bkh = (tid >> 7) * 4;         // kpair base: 0 or 4

    float acc[4][4][4];
    #pragma unroll
    for (int i = 0; i < 4; i++)
        #pragma unroll
        for (int j = 0; j < 4; j++)
            #pragma unroll
            for (int r = 0; r < 4; r++) acc[i][j][r] = 0.0f;

    float4 aq0, aq1;
    float bv0[4], bv1[4];

    // ---- prologue: load + convert tile 0 into buffer 0 ----
    {
        aq0 = *(const float4*)&X[(size_t)(m0 + ar0) * DM + ak];
        aq1 = *(const float4*)&X[(size_t)(m0 + ar1) * DM + ak];
        #pragma unroll
        for (int j = 0; j < 4; j++) {
            int kp = bkh + j;
            bv0[j] = Wd[(size_t)(2 * kp)     * DM + n0 + bn];
            bv1[j] = Wd[(size_t)(2 * kp + 1) * DM + n0 + bn];
        }
        uint32_t h, l;
        split2(aq0.x, aq0.y, h, l); Ah[0][akp    ][ar0] = h; Al[0][akp    ][ar0] = l;
        split2(aq0.z, aq0.w, h, l); Ah[0][akp + 1][ar0] = h; Al[0][akp + 1][ar0] = l;
        split2(aq1.x, aq1.y, h, l); Ah[0][akp    ][ar1] = h; Al[0][akp    ][ar1] = l;
        split2(aq1.z, aq1.w, h, l); Ah[0][akp + 1][ar1] = h; Al[0][akp + 1][ar1] = l;
        #pragma unroll
        for (int j = 0; j < 4; j++) {
            split2(bv0[j], bv1[j], h, l);
            Bh[0][bkh + j][bn] = h; Bl[0][bkh + j][bn] = l;
        }
    }
    __syncthreads();

    const int NT = DM / 16;   // 64 k-tiles
    #pragma unroll 1
    for (int t = 0; t < NT; t++) {
        const int cur = t & 1;
        const bool more = (t + 1 < NT);
        if (more) {
            const int k0 = (t + 1) * 16;
            aq0 = *(const float4*)&X[(size_t)(m0 + ar0) * DM + k0 + ak];
            aq1 = *(const float4*)&X[(size_t)(m0 + ar1) * DM + k0 + ak];
            #pragma unroll
            for (int j = 0; j < 4; j++) {
                int kp = bkh + j;
                bv0[j] = Wd[(size_t)(k0 + 2 * kp)     * DM + n0 + bn];
                bv1[j] = Wd[(size_t)(k0 + 2 * kp + 1) * DM + n0 + bn];
            }
        }

        // ---- fragments (conflict-free LDS of pre-split bf16x2) ----
        uint32_t ah[4][4], al[4][4];
        #pragma unroll
        for (int mt = 0; mt < 4; mt++) {
            const int r0 = m0w + mt * 16 + g, r1 = r0 + 8;
            ah[mt][0] = Ah[cur][t4    ][r0];  al[mt][0] = Al[cur][t4    ][r0];
            ah[mt][1] = Ah[cur][t4    ][r1];  al[mt][1] = Al[cur][t4    ][r1];
            ah[mt][2] = Ah[cur][t4 + 4][r0];  al[mt][2] = Al[cur][t4 + 4][r0];
            ah[mt][3] = Ah[cur][t4 + 4][r1];  al[mt][3] = Al[cur][t4 + 4][r1];
        }
        uint32_t bh[4][2], bl[4][2];
        #pragma unroll
        for (int nt = 0; nt < 4; nt++) {
            const int cn = n0w + nt * 8 + g;
            bh[nt][0] = Bh[cur][t4    ][cn];  bh[nt][1] = Bh[cur][t4 + 4][cn];
            bl[nt][0] = Bl[cur][t4    ][cn];  bl[nt][1] = Bl[cur][t4 + 4][cn];
        }
        // ---- 3-pass mma: hi*hi, hi*lo, lo*hi ----
        #pragma unroll
        for (int mt = 0; mt < 4; mt++)
            #pragma unroll
            for (int nt = 0; nt < 4; nt++) {
                mma_bf16(acc[mt][nt], ah[mt], bh[nt]);
                mma_bf16(acc[mt][nt], ah[mt], bl[nt]);
                mma_bf16(acc[mt][nt], al[mt], bh[nt]);
            }

        if (more) {
            const int nxt = cur ^ 1;
            uint32_t h, l;
            split2(aq0.x, aq0.y, h, l); Ah[nxt][akp    ][ar0] = h; Al[nxt][akp    ][ar0] = l;
            split2(aq0.z, aq0.w, h, l); Ah[nxt][akp + 1][ar0] = h; Al[nxt][akp + 1][ar0] = l;
            split2(aq1.x, aq1.y, h, l); Ah[nxt][akp    ][ar1] = h; Al[nxt][akp    ][ar1] = l;
            split2(aq1.z, aq1.w, h, l); Ah[nxt][akp + 1][ar1] = h; Al[nxt][akp + 1][ar1] = l;
            #pragma unroll
            for (int j = 0; j < 4; j++) {
                split2(bv0[j], bv1[j], h, l);
                Bh[nxt][bkh + j][bn] = h; Bl[nxt][bkh + j][bn] = l;
            }
        }
        __syncthreads();
    }

    // epilogue: bias + softplus (C layout identical to validated tf32 version)
    #pragma unroll
    for (int mt = 0; mt < 4; mt++) {
        const int r0 = m0 + m0w + mt * 16 + g;
        const int r1 = r0 + 8;
        #pragma unroll
        for (int nt = 0; nt < 4; nt++) {
            const int cbase = n0 + n0w + nt * 8 + 2 * t4;
            const float b0 = __ldg(&bd[cbase]), b1 = __ldg(&bd[cbase + 1]);
            float2 v0, v1;
            v0.x = softplusf(acc[mt][nt][0] + b0);
            v0.y = softplusf(acc[mt][nt][1] + b1);
            v1.x = softplusf(acc[mt][nt][2] + b0);
            v1.y = softplusf(acc[mt][nt][3] + b1);
            *(float2*)&g_delta[(size_t)r0 * DM + cbase] = v0;
            *(float2*)&g_delta[(size_t)r1 * DM + cbase] = v1;
        }
    }
}

// ---------------- kernel 2: Bm = x@Wb+bb, Cm = x@Wc+bc (N=16 each) ----------------
#define BC_BK 128
__global__ __launch_bounds__(256)
void proj_bc_kernel(const float* __restrict__ X,
                    const float* __restrict__ Wb, const float* __restrict__ bb,
                    const float* __restrict__ Wc, const float* __restrict__ bc)
{
    __shared__ float xs[16][BC_BK];    // 8KB
    __shared__ float ws[BC_BK][32];    // 16KB
    const int row0 = blockIdx.x * 16;
    const int c  = threadIdx.x & 31;   // 0..31 (0..15 -> B, 16..31 -> C)
    const int rq = threadIdx.x >> 5;   // 0..7

    float acc0 = 0.0f, acc1 = 0.0f;
    for (int k0 = 0; k0 < DM; k0 += BC_BK) {
        #pragma unroll
        for (int it = 0; it < 2; it++) {
            int i = threadIdx.x + it * 256;     // 0..511 float4s of xs
            int r  = i / (BC_BK / 4);
            int kk = i % (BC_BK / 4);
            *(float4*)&xs[r][kk * 4] =
                *(const float4*)&X[(size_t)(row0 + r) * DM + k0 + kk * 4];
        }
        for (int i = threadIdx.x; i < BC_BK * 32; i += 256) {
            int kk = i >> 5, cc = i & 31;
            ws[kk][cc] = (cc < 16) ? Wb[(size_t)(k0 + kk) * NS + cc]
                                   : Wc[(size_t)(k0 + kk) * NS + (cc - 16)];
        }
        __syncthreads();
        #pragma unroll 8
        for (int k = 0; k < BC_BK; k++) {
            float w = ws[k][c];
            acc0 += xs[rq][k] * w;
            acc1 += xs[rq + 8][k] * w;
        }
        __syncthreads();
    }
    const int r0 = row0 + rq, r1 = row0 + rq + 8;
    if (c < 16) {
        g_Bm[(size_t)r0 * NS + c] = acc0 + bb[c];
        g_Bm[(size_t)r1 * NS + c] = acc1 + bb[c];
    } else {
        g_Cm[(size_t)r0 * NS + (c - 16)] = acc0 + bc[c - 16];
        g_Cm[(size_t)r1 * NS + (c - 16)] = acc1 + bc[c - 16];
    }
}

// ---------------- kernel 3: chunked scan pass 1 (local states, h_in = 0) ----------------
__global__ __launch_bounds__(128)
void scan_pass1_kernel(const float* __restrict__ X, const float* __restrict__ A_log)
{
    const int d = blockIdx.x * 128 + threadIdx.x;
    const int c = blockIdx.y;
    const int b = blockIdx.z;

    __shared__ float Bs[CHUNK][NS];    // 2KB
    {
        const float* src = &g_Bm[((size_t)b * SEQ + c * CHUNK) * NS];
        for (int i = threadIdx.x; i < CHUNK * NS; i += 128)
            Bs[i / NS][i % NS] = src[i];
    }
    __syncthreads();

    float A2[NS];
    #pragma unroll
    for (int n = 0; n < NS; n++)
        A2[n] = -__expf(A_log[d * NS + n]) * LOG2E;

    float h[NS];
    #pragma unroll
    for (int n = 0; n < NS; n++) h[n] = 0.0f;
    float S = 0.0f;

    const size_t rowbase = ((size_t)b * SEQ + c * CHUNK) * DM + d;
    const float* dp = g_delta + rowbase;
    const float* xp = X + rowbase;

    #pragma unroll 4
    for (int t = 0; t < CHUNK; t++) {
        float dt  = dp[(size_t)t * DM];
        float xt  = xp[(size_t)t * DM];
        float dtx = dt * xt;
        S += dt;
        #pragma unroll
        for (int n = 0; n < NS; n++) {
            float barA = ex2f(dt * A2[n]);
            h[n] = barA * h[n] + dtx * Bs[t][n];
        }
    }

    const size_t base = (((size_t)b * DM + d) * NCH + c) * NS;
    #pragma unroll
    for (int n = 0; n < NS; n += 4)
        *(float4*)&g_hloc[base + n] = make_float4(h[n], h[n+1], h[n+2], h[n+3]);
    g_S[((size_t)b * DM + d) * NCH + c] = S;
}

// ---------------- kernel 4: sequential chunk combine (n-parallel) ----------------
// Latency-bound per profile (occ 20%, issue 4.7%). Unroll-8: batch the
// independent loads + ex2 ahead of the 8-FMA dependent chain.
__global__ __launch_bounds__(128)
void combine_kernel(const float* __restrict__ A_log)
{
    const int idx = blockIdx.x * 128 + threadIdx.x;   // 0..65535
    const int n  = idx & (NS - 1);
    const int bd = idx >> 4;                          // b*DM + d
    const int d  = bd & (DM - 1);

    const float A2 = -__expf(A_log[d * NS + n]) * LOG2E;
    float h = 0.0f;
    const size_t sbase = (size_t)bd * NCH;
    #pragma unroll 1
    for (int c0 = 0; c0 < NCH; c0 += 8) {
        float S[8], L[8], E[8];
        #pragma unroll
        for (int j = 0; j < 8; j++) {
            S[j] = g_S[sbase + c0 + j];
            L[j] = g_hloc[(sbase + c0 + j) * NS + n];
        }
        #pragma unroll
        for (int j = 0; j < 8; j++) E[j] = ex2f(A2 * S[j]);
        #pragma unroll
        for (int j = 0; j < 8; j++) {
            g_hin[(sbase + c0 + j) * NS + n] = h;
            h = E[j] * h + L[j];
        }
    }
}

// ---------------- kernel 5: chunked scan pass 2 (real h_in, emit y) ----------------
__global__ __launch_bounds__(128)
void scan_pass2_kernel(const float* __restrict__ X, const float* __restrict__ A_log,
                       const float* __restrict__ D_skip, float* __restrict__ out)
{
    const int d = blockIdx.x * 128 + threadIdx.x;
    const int c = blockIdx.y;
    const int b = blockIdx.z;

    __shared__ float Bs[CHUNK][NS];
    __shared__ float Cs[CHUNK][NS];
    {
        const float* srcB = &g_Bm[((size_t)b * SEQ + c * CHUNK) * NS];
        const float* srcC = &g_Cm[((size_t)b * SEQ + c * CHUNK) * NS];
        for (int i = threadIdx.x; i < CHUNK * NS; i += 128) {
            Bs[i / NS][i % NS] = srcB[i];
            Cs[i / NS][i % NS] = srcC[i];
        }
    }
    __syncthreads();

    float A2[NS];
    #pragma unroll
    for (int n = 0; n < NS; n++)
        A2[n] = -__expf(A_log[d * NS + n]) * LOG2E;

    float h[NS];
    {
        const size_t base = (((size_t)b * DM + d) * NCH + c) * NS;
        #pragma unroll
        for (int n = 0; n < NS; n += 4) {
            float4 v = *(const float4*)&g_hin[base + n];
            h[n] = v.x; h[n+1] = v.y; h[n+2] = v.z; h[n+3] = v.w;
        }
    }
    const float dsk = D_skip[d];

    const size_t rowbase = ((size_t)b * SEQ + c * CHUNK) * DM + d;
    const float* dp = g_delta + rowbase;
    const float* xp = X + rowbase;
    float* op = out + rowbase;

    #pragma unroll 4
    for (int t = 0; t < CHUNK; t++) {
        float dt  = dp[(size_t)t * DM];
        float xt  = xp[(size_t)t * DM];
        float dtx = dt * xt;
        float y = xt * dsk;
        #pragma unroll
        for (int n = 0; n < NS; n++) {
            float barA = ex2f(dt * A2[n]);
            h[n] = barA * h[n] + dtx * Bs[t][n];
            y += h[n] * Cs[t][n];
        }
        op[(size_t)t * DM] = y;
    }
}

// ---------------- launch ----------------
extern "C" void kernel_launch(void* const* d_in, const int* in_sizes, int n_in,
                              void* d_out, int out_size)
{
    const float* x      = (const float*)d_in[0];
    const float* A_log  = (const float*)d_in[1];
    const float* D_skip = (const float*)d_in[2];
    const float* Wd     = (const float*)d_in[3];
    const float* bd     = (const float*)d_in[4];
    const float* Wb     = (const float*)d_in[5];
    const float* bb     = (const float*)d_in[6];
    const float* Wc     = (const float*)d_in[7];
    const float* bc     = (const float*)d_in[8];
    float* out = (float*)d_out;

    gemm_delta_kernel<<<dim3(DM / 128, MROWS / 128), 256>>>(x, Wd, bd);
    proj_bc_kernel<<<MROWS / 16, 256>>>(x, Wb, bb, Wc, bc);
    scan_pass1_kernel<<<dim3(DM / 128, NCH, B_SZ), 128>>>(x, A_log);
    combine_kernel<<<(B_SZ * DM * NS) / 128, 128>>>(A_log);
    scan_pass2_kernel<<<dim3(DM / 128, NCH, B_SZ), 128>>>(x, A_log, D_skip, out);
}